// round 13
// baseline (speedup 1.0000x reference)
#include <cuda_runtime.h>

// SegGPS_66949950210076
// out[b] = sum_m prod_l eps[idx[b,l], m, l, nup[b,l], ndn[b,l]]
// B=8192, L=64, M=64, LOCAL_DIM=4, eps (4,64,64,65,65) fp32.
//
// R10: 3 kernels. bounds (per-l (nup,ndn) bounding boxes via packed-byte
// CTA reduce + 256 atomicMin) -> box transpose into T[cell][idx][m]
// (256B m-contiguous, L2-resident) -> gather (warp/batch, float4 lane-split)
// which also restores the bounds sentinels for the next launch.
// g_bounds statically initialized to the atomicMin identity (64).

#define B_SZ   8192
#define L_SZ   64
#define IDX_STRIDE 17305600   // M*L*65*65
#define M_STRIDE   270400     // L*65*65
#define L_STRIDE   4225       // 65*65
#define CELLS  89440          // sum_{k=1..64} k^2
#define T_ELEMS (CELLS * 256)

__device__ __align__(256) float g_T[T_ELEMS];  // 91.6 MB scratch (static)

// g_bounds[l] = { min nup, 64-max nup, min ndn, 64-max ndn }  (uint4-aligned)
#define S8  64u,64u,64u,64u,64u,64u,64u,64u
#define S64 S8,S8,S8,S8,S8,S8,S8,S8
__device__ __align__(16) unsigned g_bounds[L_SZ][4] = { S64, S64, S64, S64 };

__device__ __forceinline__ int cell_off(int l) {
    return l * (l + 1) * (2 * l + 1) / 6;      // sum_{j=1..l} j^2
}
__device__ __forceinline__ float4 mul4(float4 a, float4 b) {
    return make_float4(a.x * b.x, a.y * b.y, a.z * b.z, a.w * b.w);
}

// Per-warp dtype probe. Indices are logically int64 (ref) but JAX x64-off
// emits int32. Under int64 LE every odd 32-bit word is 0 (values < 4); under
// int32 odd words are random in [0,4). Probe 64 odd words of a fixed
// 128-word window within the first 524288 words (in-bounds either way).
// P(false int64 | int32) = 0.25^64 per warp.
__device__ __forceinline__ int probe_is_int32(const unsigned* __restrict__ w,
                                              int b, int lane) {
    int base = (b & 4095) * 128;
    unsigned x = w[base + 2 * lane + 1] | w[base + 64 + 2 * lane + 1];
    return __ballot_sync(0xffffffffu, x != 0u) != 0u;
}

// Per-warp scan of one batch: two ballots cover all 64 sites.
__device__ __forceinline__ void scan_batch_raw(
    const void* idx_raw, int is32, int b, int lane,
    int& v0, int& v1, int& nup0, int& ndn0, int& nup1, int& ndn1)
{
    if (is32) {
        const int* p = (const int*)idx_raw + b * L_SZ;
        v0 = p[lane];  v1 = p[lane + 32];
    } else {
        const long long* p = (const long long*)idx_raw + (size_t)b * L_SZ;
        v0 = (int)p[lane];  v1 = (int)p[lane + 32];
    }
    unsigned bu0 = __ballot_sync(0xffffffffu, v0 & 1);
    unsigned bd0 = __ballot_sync(0xffffffffu, v0 & 2);
    unsigned bu1 = __ballot_sync(0xffffffffu, v1 & 1);
    unsigned bd1 = __ballot_sync(0xffffffffu, v1 & 2);
    unsigned mlt = (1u << lane) - 1u;
    nup0 = __popc(bu0 & mlt);               ndn0 = __popc(bd0 & mlt);
    nup1 = __popc(bu0) + __popc(bu1 & mlt); ndn1 = __popc(bd0) + __popc(bd1 & mlt);
}

// ---- per-l bounding boxes: CTA-reduce 8 batches, 256 atomicMin total ----
__global__ __launch_bounds__(256) void bounds_kernel(const void* __restrict__ idx_raw) {
    __shared__ unsigned red[8][64];

    const int lane = threadIdx.x & 31;
    const int w    = threadIdx.x >> 5;
    const int b    = blockIdx.x * 8 + w;

    int is32 = probe_is_int32((const unsigned*)idx_raw, b, lane);
    int v0, v1, nu0, nd0, nu1, nd1;
    scan_batch_raw(idx_raw, is32, b, lane, v0, v1, nu0, nd0, nu1, nd1);
    (void)v0; (void)v1;

    // pack (nup, 64-nup, ndn, 64-ndn) as bytes; byte-wise min == field min
    red[w][lane]      = (unsigned)(nu0 | ((64 - nu0) << 8) |
                                   (nd0 << 16) | ((64 - nd0) << 24));
    red[w][lane + 32] = (unsigned)(nu1 | ((64 - nu1) << 8) |
                                   (nd1 << 16) | ((64 - nd1) << 24));
    __syncthreads();

    if (threadIdx.x < 64) {
        const int l = threadIdx.x;
        unsigned r = red[0][l];
        #pragma unroll
        for (int k = 1; k < 8; k++) r = __vminu4(r, red[k][l]);
        atomicMin(&g_bounds[l][0],  r        & 255u);   // min nup
        atomicMin(&g_bounds[l][1], (r >>  8) & 255u);   // 64 - max nup
        atomicMin(&g_bounds[l][2], (r >> 16) & 255u);   // min ndn
        atomicMin(&g_bounds[l][3],  r >> 24        );   // 64 - max ndn
    }
}

// ---- box transpose: CTA per (l, nup, idx); smem-coalesced, box-restricted --
__global__ __launch_bounds__(256) void transpose_kernel(const float* __restrict__ eps) {
    const int l = blockIdx.x, nup = blockIdx.y, idx = blockIdx.z;
    if (nup > l) return;

    const uint4 bb = *(const uint4*)&g_bounds[l][0];    // one 16B load
    const int amin = (int)bb.x, amax = 64 - (int)bb.y;
    if (nup < amin || nup > amax) return;
    const int cmin = (int)bb.z;
    int cmax = 64 - (int)bb.w;
    if (cmax > l) cmax = l;
    const int W = cmax - cmin + 1;         // 1..65
    if (W <= 0) return;

    const int nv = l + 1;
    const int cellbase = cell_off(l) + nup * nv;

    __shared__ float sm[64][65];           // [m][ndn-cmin]

    const int tid = threadIdx.x;
    const int c64 = tid & 63;
    const int r4  = tid >> 6;

    // read: columns cmin..cmax contiguous along ndn -> coalesced
    const float* src = eps + idx * IDX_STRIDE + l * L_STRIDE + nup * 65 + cmin;
    if (c64 < W) {
        #pragma unroll
        for (int mb = 0; mb < 64; mb += 4) {
            int m = mb + r4;
            sm[m][c64] = src[m * M_STRIDE + c64];
        }
    }
    __syncthreads();

    // write: 256B m-contiguous per box cell
    float* dst = g_T + (size_t)cellbase * 256 + idx * 64;
    for (int nb = 0; nb < W; nb += 4) {
        int k = nb + r4;                    // ndn - cmin
        if (k < W)
            dst[(cmin + k) * 256 + c64] = sm[c64][k];
    }
}

// ---- gather: warp per batch; float4, lane-split; restores bound sentinels --
__global__ __launch_bounds__(256) void seggps_kernel(
    const void* __restrict__ idx_raw,
    float*      __restrict__ out)
{
    __shared__ int soffs[8][64];

    // restore atomicMin identity for next launch (transpose already consumed
    // bounds: kernels are stream-ordered). One CTA, coalesced 256-word write.
    if (blockIdx.x == 0) ((unsigned*)g_bounds)[threadIdx.x] = 64u;

    const int lane = threadIdx.x & 31;
    const int w    = threadIdx.x >> 5;
    const int b    = blockIdx.x * 8 + w;

    int is32 = probe_is_int32((const unsigned*)idx_raw, b, lane);
    int v0, v1, nu0, nd0, nu1, nd1;
    scan_batch_raw(idx_raw, is32, b, lane, v0, v1, nu0, nd0, nu1, nd1);
    int c0 = cell_off(lane)      + nu0 * (lane + 1)  + nd0;
    int c1 = cell_off(lane + 32) + nu1 * (lane + 33) + nd1;
    soffs[w][lane]      = c0 * 256 + v0 * 64;
    soffs[w][lane + 32] = c1 * 256 + v1 * 64;
    __syncwarp();

    const int half = lane >> 4;             // 0: even sites, 1: odd sites
    const int q    = lane & 15;             // m-quad (4 floats)

    float4 a0 = make_float4(1.f, 1.f, 1.f, 1.f), a1 = a0, a2 = a0, a3 = a0;
    #pragma unroll
    for (int i = 0; i < 32; i += 4) {
        float4 x0 = __ldg((const float4*)(g_T + soffs[w][2 * (i + 0) + half]) + q);
        float4 x1 = __ldg((const float4*)(g_T + soffs[w][2 * (i + 1) + half]) + q);
        float4 x2 = __ldg((const float4*)(g_T + soffs[w][2 * (i + 2) + half]) + q);
        float4 x3 = __ldg((const float4*)(g_T + soffs[w][2 * (i + 3) + half]) + q);
        a0 = mul4(a0, x0);
        a1 = mul4(a1, x1);
        a2 = mul4(a2, x2);
        a3 = mul4(a3, x3);
    }
    float4 p = mul4(mul4(a0, a1), mul4(a2, a3));

    float4 o;
    o.x = __shfl_xor_sync(0xffffffffu, p.x, 16);
    o.y = __shfl_xor_sync(0xffffffffu, p.y, 16);
    o.z = __shfl_xor_sync(0xffffffffu, p.z, 16);
    o.w = __shfl_xor_sync(0xffffffffu, p.w, 16);
    p = mul4(p, o);

    float s = (p.x + p.y) + (p.z + p.w);
    #pragma unroll
    for (int off = 8; off; off >>= 1) s += __shfl_xor_sync(0xffffffffu, s, off);
    if (lane == 0) out[b] = s;
}

extern "C" void kernel_launch(void* const* d_in, const int* in_sizes, int n_in,
                              void* d_out, int out_size)
{
    const void*  idx = d_in[0];                 // indices (B,L) int32 or int64
    const float* eps = (const float*)d_in[1];   // epsilon fp32
    float* out = (float*)d_out;
    (void)in_sizes; (void)n_in; (void)out_size;

    bounds_kernel<<<B_SZ / 8, 256>>>(idx);
    transpose_kernel<<<dim3(64, 64, 4), 256>>>(eps);
    seggps_kernel<<<B_SZ / 8, 256>>>(idx, out);
}

// round 14
// speedup vs baseline: 2.5569x; 2.5569x over previous
#include <cuda_runtime.h>

// SegGPS_66949950210076
// out[b] = sum_m prod_l eps[idx[b,l], m, l, nup[b,l], ndn[b,l]]
// B=8192, L=64, M=64, LOCAL_DIM=4, eps (4,64,64,65,65) fp32.
//
// R11: 3 kernels. bounds (hierarchical: 8 batches/warp in registers ->
// smem -> 32k atomicMin on FIELD-MAJOR g_bounds[4][64]) -> box transpose
// into T[cell][idx][m] (256B m-contiguous, L2-resident) -> gather
// (warp/batch, float4 lane-split) which restores the bounds sentinels.

#define B_SZ   8192
#define L_SZ   64
#define IDX_STRIDE 17305600   // M*L*65*65
#define M_STRIDE   270400     // L*65*65
#define L_STRIDE   4225       // 65*65
#define CELLS  89440          // sum_{k=1..64} k^2
#define T_ELEMS (CELLS * 256)

__device__ __align__(256) float g_T[T_ELEMS];  // 91.6 MB scratch (static)

// g_bounds[0][l]=min nup, [1][l]=64-max nup, [2][l]=min ndn, [3][l]=64-max ndn
// Field-major: warp-wide atomics to one field touch 2 lines, and each line
// serves only one field's traffic (R10's [l][4] packing quadrupled per-line
// atomic pressure and serialized at the LTS).
#define S8  64u,64u,64u,64u,64u,64u,64u,64u
#define S64 S8,S8,S8,S8,S8,S8,S8,S8
__device__ unsigned g_bounds[4][L_SZ] = { S64, S64, S64, S64 };

__device__ __forceinline__ int cell_off(int l) {
    return l * (l + 1) * (2 * l + 1) / 6;      // sum_{j=1..l} j^2
}
__device__ __forceinline__ float4 mul4(float4 a, float4 b) {
    return make_float4(a.x * b.x, a.y * b.y, a.z * b.z, a.w * b.w);
}

// Per-warp dtype probe. Indices are logically int64 (ref) but JAX x64-off
// emits int32. Under int64 LE every odd 32-bit word is 0 (values < 4); under
// int32 odd words are random in [0,4). Probe 64 odd words of a fixed
// 128-word window within the first 524288 words (in-bounds either way).
// P(false int64 | int32) = 0.25^64 per warp.
__device__ __forceinline__ int probe_is_int32(const unsigned* __restrict__ w,
                                              int b, int lane) {
    int base = (b & 4095) * 128;
    unsigned x = w[base + 2 * lane + 1] | w[base + 64 + 2 * lane + 1];
    return __ballot_sync(0xffffffffu, x != 0u) != 0u;
}

// Per-warp scan of one batch: two ballots cover all 64 sites.
__device__ __forceinline__ void scan_batch_raw(
    const void* idx_raw, int is32, int b, int lane,
    int& v0, int& v1, int& nup0, int& ndn0, int& nup1, int& ndn1)
{
    if (is32) {
        const int* p = (const int*)idx_raw + b * L_SZ;
        v0 = p[lane];  v1 = p[lane + 32];
    } else {
        const long long* p = (const long long*)idx_raw + (size_t)b * L_SZ;
        v0 = (int)p[lane];  v1 = (int)p[lane + 32];
    }
    unsigned bu0 = __ballot_sync(0xffffffffu, v0 & 1);
    unsigned bd0 = __ballot_sync(0xffffffffu, v0 & 2);
    unsigned bu1 = __ballot_sync(0xffffffffu, v1 & 1);
    unsigned bd1 = __ballot_sync(0xffffffffu, v1 & 2);
    unsigned mlt = (1u << lane) - 1u;
    nup0 = __popc(bu0 & mlt);               ndn0 = __popc(bd0 & mlt);
    nup1 = __popc(bu0) + __popc(bu1 & mlt); ndn1 = __popc(bd0) + __popc(bd1 & mlt);
}

// ---- per-l bounding boxes: 8 batches/warp in regs -> smem -> atomicMin ----
__global__ __launch_bounds__(256) void bounds_kernel(const void* __restrict__ idx_raw) {
    __shared__ unsigned red[8][64];

    const int lane = threadIdx.x & 31;
    const int w    = threadIdx.x >> 5;
    const int b0   = blockIdx.x * 64 + w * 8;       // 8 batches per warp

    int is32 = probe_is_int32((const unsigned*)idx_raw, b0, lane);

    unsigned acc0 = 0xFFFFFFFFu, acc1 = 0xFFFFFFFFu;
    #pragma unroll
    for (int i = 0; i < 8; i++) {
        int v0, v1, nu0, nd0, nu1, nd1;
        scan_batch_raw(idx_raw, is32, b0 + i, lane, v0, v1, nu0, nd0, nu1, nd1);
        (void)v0; (void)v1;
        // pack (nup, 64-nup, ndn, 64-ndn) bytes; byte-wise min == field min
        unsigned r0 = (unsigned)(nu0 | ((64 - nu0) << 8) |
                                 (nd0 << 16) | ((64 - nd0) << 24));
        unsigned r1 = (unsigned)(nu1 | ((64 - nu1) << 8) |
                                 (nd1 << 16) | ((64 - nd1) << 24));
        acc0 = __vminu4(acc0, r0);
        acc1 = __vminu4(acc1, r1);
    }
    red[w][lane]      = acc0;
    red[w][lane + 32] = acc1;
    __syncthreads();

    if (threadIdx.x < 64) {
        const int l = threadIdx.x;
        unsigned r = red[0][l];
        #pragma unroll
        for (int k = 1; k < 8; k++) r = __vminu4(r, red[k][l]);
        atomicMin(&g_bounds[0][l],  r        & 255u);   // min nup
        atomicMin(&g_bounds[1][l], (r >>  8) & 255u);   // 64 - max nup
        atomicMin(&g_bounds[2][l], (r >> 16) & 255u);   // min ndn
        atomicMin(&g_bounds[3][l],  r >> 24        );   // 64 - max ndn
    }
}

// ---- box transpose: CTA per (l, nup, idx); smem-coalesced, box-restricted --
__global__ __launch_bounds__(256) void transpose_kernel(const float* __restrict__ eps) {
    const int l = blockIdx.x, nup = blockIdx.y, idx = blockIdx.z;
    if (nup > l) return;

    const int amin =      (int)g_bounds[0][l];
    const int amax = 64 - (int)g_bounds[1][l];
    if (nup < amin || nup > amax) return;
    const int cmin = (int)g_bounds[2][l];
    int cmax = 64 - (int)g_bounds[3][l];
    if (cmax > l) cmax = l;
    const int W = cmax - cmin + 1;         // 1..65
    if (W <= 0) return;

    const int nv = l + 1;
    const int cellbase = cell_off(l) + nup * nv;

    __shared__ float sm[64][65];           // [m][ndn-cmin]

    const int tid = threadIdx.x;
    const int c64 = tid & 63;
    const int r4  = tid >> 6;

    // read: columns cmin..cmax contiguous along ndn -> coalesced
    const float* src = eps + idx * IDX_STRIDE + l * L_STRIDE + nup * 65 + cmin;
    if (c64 < W) {
        #pragma unroll
        for (int mb = 0; mb < 64; mb += 4) {
            int m = mb + r4;
            sm[m][c64] = src[m * M_STRIDE + c64];
        }
    }
    __syncthreads();

    // write: 256B m-contiguous per box cell
    float* dst = g_T + (size_t)cellbase * 256 + idx * 64;
    for (int nb = 0; nb < W; nb += 4) {
        int k = nb + r4;                    // ndn - cmin
        if (k < W)
            dst[(cmin + k) * 256 + c64] = sm[c64][k];
    }
}

// ---- gather: warp per batch; float4, lane-split; restores bound sentinels --
__global__ __launch_bounds__(256) void seggps_kernel(
    const void* __restrict__ idx_raw,
    float*      __restrict__ out)
{
    __shared__ int soffs[8][64];

    // restore atomicMin identity for next launch (transpose already consumed
    // bounds; kernels are stream-ordered). One CTA, coalesced 256-word write.
    if (blockIdx.x == 0) ((unsigned*)g_bounds)[threadIdx.x] = 64u;

    const int lane = threadIdx.x & 31;
    const int w    = threadIdx.x >> 5;
    const int b    = blockIdx.x * 8 + w;

    int is32 = probe_is_int32((const unsigned*)idx_raw, b, lane);
    int v0, v1, nu0, nd0, nu1, nd1;
    scan_batch_raw(idx_raw, is32, b, lane, v0, v1, nu0, nd0, nu1, nd1);
    int c0 = cell_off(lane)      + nu0 * (lane + 1)  + nd0;
    int c1 = cell_off(lane + 32) + nu1 * (lane + 33) + nd1;
    soffs[w][lane]      = c0 * 256 + v0 * 64;
    soffs[w][lane + 32] = c1 * 256 + v1 * 64;
    __syncwarp();

    const int half = lane >> 4;             // 0: even sites, 1: odd sites
    const int q    = lane & 15;             // m-quad (4 floats)

    float4 a0 = make_float4(1.f, 1.f, 1.f, 1.f), a1 = a0, a2 = a0, a3 = a0;
    #pragma unroll
    for (int i = 0; i < 32; i += 4) {
        float4 x0 = __ldg((const float4*)(g_T + soffs[w][2 * (i + 0) + half]) + q);
        float4 x1 = __ldg((const float4*)(g_T + soffs[w][2 * (i + 1) + half]) + q);
        float4 x2 = __ldg((const float4*)(g_T + soffs[w][2 * (i + 2) + half]) + q);
        float4 x3 = __ldg((const float4*)(g_T + soffs[w][2 * (i + 3) + half]) + q);
        a0 = mul4(a0, x0);
        a1 = mul4(a1, x1);
        a2 = mul4(a2, x2);
        a3 = mul4(a3, x3);
    }
    float4 p = mul4(mul4(a0, a1), mul4(a2, a3));

    float4 o;
    o.x = __shfl_xor_sync(0xffffffffu, p.x, 16);
    o.y = __shfl_xor_sync(0xffffffffu, p.y, 16);
    o.z = __shfl_xor_sync(0xffffffffu, p.z, 16);
    o.w = __shfl_xor_sync(0xffffffffu, p.w, 16);
    p = mul4(p, o);

    float s = (p.x + p.y) + (p.z + p.w);
    #pragma unroll
    for (int off = 8; off; off >>= 1) s += __shfl_xor_sync(0xffffffffu, s, off);
    if (lane == 0) out[b] = s;
}

extern "C" void kernel_launch(void* const* d_in, const int* in_sizes, int n_in,
                              void* d_out, int out_size)
{
    const void*  idx = d_in[0];                 // indices (B,L) int32 or int64
    const float* eps = (const float*)d_in[1];   // epsilon fp32
    float* out = (float*)d_out;
    (void)in_sizes; (void)n_in; (void)out_size;

    bounds_kernel<<<B_SZ / 64, 256>>>(idx);
    transpose_kernel<<<dim3(64, 64, 4), 256>>>(eps);
    seggps_kernel<<<B_SZ / 8, 256>>>(idx, out);
}